// round 3
// baseline (speedup 1.0000x reference)
#include <cuda_runtime.h>
#include <math.h>
#include <stdint.h>

// Problem constants (fixed by the reference)
#define S_LEN   2048
#define BATCH   2
#define DMODEL  1024
#define NHEAD   16
#define DHEAD   64
#define MROWS   (S_LEN * BATCH)   // 4096 rows for the projection GEMMs

// Scratch: __device__ globals (no allocation allowed). 4 x 16MB = 64MB.
__device__ float g_q[S_LEN * BATCH * DMODEL];
__device__ float g_k[S_LEN * BATCH * DMODEL];
__device__ float g_v[S_LEN * BATCH * DMODEL];
__device__ float g_attn[S_LEN * BATCH * DMODEL];

// ---------------------------------------------------------------------------
// Helpers
// ---------------------------------------------------------------------------
__device__ __forceinline__ float tf32_rna(float x) {
    uint32_t r;
    asm("cvt.rna.tf32.f32 %0, %1;" : "=r"(r) : "f"(x));
    return __uint_as_float(r);
}

// m16n8k8 tf32 mma, fp32 accumulate (family-invariant, works on .target sm_103)
__device__ __forceinline__ void mma8(float c[4], const uint32_t a[4],
                                     const uint32_t b[2]) {
    asm volatile(
        "mma.sync.aligned.m16n8k8.row.col.f32.tf32.tf32.f32 "
        "{%0,%1,%2,%3}, {%4,%5,%6,%7}, {%8,%9}, {%0,%1,%2,%3};\n"
        : "+f"(c[0]), "+f"(c[1]), "+f"(c[2]), "+f"(c[3])
        : "r"(a[0]), "r"(a[1]), "r"(a[2]), "r"(a[3]),
          "r"(b[0]), "r"(b[1]));
}

// ---------------------------------------------------------------------------
// Tensor-core TF32 projection GEMM: Y[m,n] = sum_k X[m,k]*W[n,k] + bias[n]
// 3xTF32 Dekker split for fp32-level accuracy.
// CTA tile 128x128, BK=32, 256 threads (8 warps, each warp 64x32).
// Smem: A/B hi+lo tiles, padded stride 36 floats for conflict-free frag LDS.
// ---------------------------------------------------------------------------
#define PADK 36
#define GSM_FLOATS (4 * 128 * PADK)
#define GSM_BYTES  (GSM_FLOATS * 4)   // 73728

__global__ void __launch_bounds__(256)
gemm_tc_kernel(const float* __restrict__ X, const float* __restrict__ W,
               const float* __restrict__ bias, float* __restrict__ Y,
               int M, int N, int K)
{
    extern __shared__ float sm[];
    float* Ahi = sm;
    float* Alo = Ahi + 128 * PADK;
    float* Bhi = Alo + 128 * PADK;
    float* Blo = Bhi + 128 * PADK;

    const int tid  = threadIdx.x;
    const int lane = tid & 31;
    const int w    = tid >> 5;
    const int wm   = w >> 2;      // 0..1 : warp row (64 rows each)
    const int wn   = w & 3;       // 0..3 : warp col (32 cols each)
    const int m0   = blockIdx.y * 128;
    const int n0   = blockIdx.x * 128;
    const int g    = lane >> 2;   // 0..7
    const int tg   = lane & 3;    // 0..3

    float c[4][4][4] = {};        // [mt][nt][frag]

    // Global->smem mapping: 4 passes; warp covers 4 full 128B rows per pass.
    const int lr = tid >> 3;          // 0..31
    const int lc = (tid & 7) * 4;     // 0..28 (float col)

    for (int k0 = 0; k0 < K; k0 += 32) {
        #pragma unroll
        for (int p = 0; p < 4; p++) {
            const int row = lr + p * 32;
            const int so  = row * PADK + lc;
            {
                float4 x = *(const float4*)(X + (size_t)(m0 + row) * K + k0 + lc);
                float4 h, l;
                h.x = tf32_rna(x.x); l.x = x.x - h.x;
                h.y = tf32_rna(x.y); l.y = x.y - h.y;
                h.z = tf32_rna(x.z); l.z = x.z - h.z;
                h.w = tf32_rna(x.w); l.w = x.w - h.w;
                *(float4*)&Ahi[so] = h;
                *(float4*)&Alo[so] = l;
            }
            {
                float4 x = *(const float4*)(W + (size_t)(n0 + row) * K + k0 + lc);
                float4 h, l;
                h.x = tf32_rna(x.x); l.x = x.x - h.x;
                h.y = tf32_rna(x.y); l.y = x.y - h.y;
                h.z = tf32_rna(x.z); l.z = x.z - h.z;
                h.w = tf32_rna(x.w); l.w = x.w - h.w;
                *(float4*)&Bhi[so] = h;
                *(float4*)&Blo[so] = l;
            }
        }
        __syncthreads();

        #pragma unroll
        for (int ks = 0; ks < 4; ks++) {
            const int kk = ks * 8;
            uint32_t ah[4][4], al[4][4];
            #pragma unroll
            for (int mt = 0; mt < 4; mt++) {
                const int r = (wm * 64 + mt * 16 + g) * PADK + kk + tg;
                ah[mt][0] = __float_as_uint(Ahi[r]);
                ah[mt][1] = __float_as_uint(Ahi[r + 8 * PADK]);
                ah[mt][2] = __float_as_uint(Ahi[r + 4]);
                ah[mt][3] = __float_as_uint(Ahi[r + 8 * PADK + 4]);
                al[mt][0] = __float_as_uint(Alo[r]);
                al[mt][1] = __float_as_uint(Alo[r + 8 * PADK]);
                al[mt][2] = __float_as_uint(Alo[r + 4]);
                al[mt][3] = __float_as_uint(Alo[r + 8 * PADK + 4]);
            }
            uint32_t bh[4][2], bl[4][2];
            #pragma unroll
            for (int nt = 0; nt < 4; nt++) {
                const int r = (wn * 32 + nt * 8 + g) * PADK + kk + tg;
                bh[nt][0] = __float_as_uint(Bhi[r]);
                bh[nt][1] = __float_as_uint(Bhi[r + 4]);
                bl[nt][0] = __float_as_uint(Blo[r]);
                bl[nt][1] = __float_as_uint(Blo[r + 4]);
            }
            #pragma unroll
            for (int mt = 0; mt < 4; mt++)
                #pragma unroll
                for (int nt = 0; nt < 4; nt++) {
                    mma8(c[mt][nt], ah[mt], bh[nt]);  // hi*hi
                    mma8(c[mt][nt], ah[mt], bl[nt]);  // hi*lo
                    mma8(c[mt][nt], al[mt], bh[nt]);  // lo*hi
                }
        }
        __syncthreads();
    }

    // Epilogue: per-thread C fragment -> gmem with bias
    #pragma unroll
    for (int mt = 0; mt < 4; mt++) {
        const int r0 = m0 + wm * 64 + mt * 16 + g;
        #pragma unroll
        for (int nt = 0; nt < 4; nt++) {
            const int cb = n0 + wn * 32 + nt * 8 + tg * 2;
            float2 bv = *(const float2*)(bias + cb);
            float2 v0, v1;
            v0.x = c[mt][nt][0] + bv.x; v0.y = c[mt][nt][1] + bv.y;
            v1.x = c[mt][nt][2] + bv.x; v1.y = c[mt][nt][3] + bv.y;
            *(float2*)(Y + (size_t)r0 * N + cb)       = v0;
            *(float2*)(Y + (size_t)(r0 + 8) * N + cb) = v1;
        }
    }
}

// ---------------------------------------------------------------------------
// Flash-attention: one thread per query row, fp32, float4 smem reads.
// ---------------------------------------------------------------------------
__global__ void __launch_bounds__(128)
attn_kernel(const float* __restrict__ Q, const float* __restrict__ Kp,
            const float* __restrict__ Vp, float* __restrict__ O)
{
    const int t    = threadIdx.x;
    const int qrow = blockIdx.x * 128 + t;
    const int hb   = blockIdx.y;
    const int h    = hb >> 1;
    const int b    = hb & 1;

    const size_t head_off = (size_t)h * DHEAD;

    float4 q4[16];
    {
        const float4* qp = (const float4*)(Q + ((size_t)qrow * BATCH + b) * DMODEL + head_off);
        #pragma unroll
        for (int i = 0; i < 16; i++) q4[i] = qp[i];
    }

    float4 o4[16];
    #pragma unroll
    for (int i = 0; i < 16; i++) o4[i] = make_float4(0.f, 0.f, 0.f, 0.f);
    float m = -1e30f;
    float l = 0.0f;
    const float scale = 0.125f;  // 1/sqrt(64)

    __shared__ __align__(16) float Ks[64][DHEAD];
    __shared__ __align__(16) float Vs[64][DHEAD];

    for (int kb = 0; kb < S_LEN; kb += 64) {
        __syncthreads();
        {
            const int f  = (t & 15) * 4;
            const int r0 = t >> 4;
            #pragma unroll
            for (int rr = 0; rr < 8; rr++) {
                const int r = r0 + rr * 8;
                const size_t gofs = ((size_t)(kb + r) * BATCH + b) * DMODEL + head_off + f;
                *(float4*)&Ks[r][f] = *(const float4*)(Kp + gofs);
                *(float4*)&Vs[r][f] = *(const float4*)(Vp + gofs);
            }
        }
        __syncthreads();

        #pragma unroll 2
        for (int j = 0; j < 64; j++) {
            const float4* kr = (const float4*)&Ks[j][0];
            float s = 0.0f;
            #pragma unroll
            for (int i = 0; i < 16; i++) {
                float4 kv = kr[i];
                s += q4[i].x * kv.x + q4[i].y * kv.y
                   + q4[i].z * kv.z + q4[i].w * kv.w;
            }
            s *= scale;

            const float4* vr = (const float4*)&Vs[j][0];
            if (s > m) {
                const float corr = __expf(m - s);
                m = s;
                l = l * corr + 1.0f;
                #pragma unroll
                for (int i = 0; i < 16; i++) {
                    float4 vv = vr[i];
                    o4[i].x = o4[i].x * corr + vv.x;
                    o4[i].y = o4[i].y * corr + vv.y;
                    o4[i].z = o4[i].z * corr + vv.z;
                    o4[i].w = o4[i].w * corr + vv.w;
                }
            } else {
                const float p = __expf(s - m);
                l += p;
                #pragma unroll
                for (int i = 0; i < 16; i++) {
                    float4 vv = vr[i];
                    o4[i].x += p * vv.x;
                    o4[i].y += p * vv.y;
                    o4[i].z += p * vv.z;
                    o4[i].w += p * vv.w;
                }
            }
        }
    }

    const float inv = 1.0f / l;
    float4* op = (float4*)(O + ((size_t)qrow * BATCH + b) * DMODEL + head_off);
    #pragma unroll
    for (int i = 0; i < 16; i++) {
        float4 r;
        r.x = o4[i].x * inv; r.y = o4[i].y * inv;
        r.z = o4[i].z * inv; r.w = o4[i].w * inv;
        op[i] = r;
    }
}

// ---------------------------------------------------------------------------
extern "C" void kernel_launch(void* const* d_in, const int* in_sizes, int n_in,
                              void* d_out, int out_size)
{
    (void)in_sizes; (void)n_in; (void)out_size;
    const float* query = (const float*)d_in[0];
    const float* key   = (const float*)d_in[1];
    const float* value = (const float*)d_in[2];
    const float* Wq    = (const float*)d_in[3];
    const float* bq    = (const float*)d_in[4];
    const float* Wk    = (const float*)d_in[5];
    const float* bk    = (const float*)d_in[6];
    const float* Wv    = (const float*)d_in[7];
    const float* bv    = (const float*)d_in[8];
    const float* Wo    = (const float*)d_in[9];
    const float* bo    = (const float*)d_in[10];
    float* out = (float*)d_out;

    float *qp, *kp, *vp, *ap;
    cudaGetSymbolAddress((void**)&qp, g_q);
    cudaGetSymbolAddress((void**)&kp, g_k);
    cudaGetSymbolAddress((void**)&vp, g_v);
    cudaGetSymbolAddress((void**)&ap, g_attn);

    cudaFuncSetAttribute(gemm_tc_kernel,
                         cudaFuncAttributeMaxDynamicSharedMemorySize, GSM_BYTES);

    dim3 ggrid(DMODEL / 128, MROWS / 128);   // (8, 32)
    gemm_tc_kernel<<<ggrid, 256, GSM_BYTES>>>(query, Wq, bq, qp, MROWS, DMODEL, DMODEL);
    gemm_tc_kernel<<<ggrid, 256, GSM_BYTES>>>(key,   Wk, bk, kp, MROWS, DMODEL, DMODEL);
    gemm_tc_kernel<<<ggrid, 256, GSM_BYTES>>>(value, Wv, bv, vp, MROWS, DMODEL, DMODEL);

    dim3 agrid(S_LEN / 128, NHEAD * BATCH);  // (16, 32)
    attn_kernel<<<agrid, 128>>>(qp, kp, vp, ap);

    gemm_tc_kernel<<<ggrid, 256, GSM_BYTES>>>(ap, Wo, bo, out, MROWS, DMODEL, DMODEL);
}

// round 4
// speedup vs baseline: 1.7688x; 1.7688x over previous
#include <cuda_runtime.h>
#include <math.h>
#include <stdint.h>

// Problem constants (fixed by the reference)
#define S_LEN   2048
#define BATCH   2
#define DMODEL  1024
#define NHEAD   16
#define DHEAD   64
#define MROWS   (S_LEN * BATCH)

// Scratch (no allocation allowed)
__device__ float g_q[S_LEN * BATCH * DMODEL];
__device__ float g_k[S_LEN * BATCH * DMODEL];
__device__ float g_v[S_LEN * BATCH * DMODEL];
__device__ float g_attn[S_LEN * BATCH * DMODEL];

// ---------------------------------------------------------------------------
// Helpers
// ---------------------------------------------------------------------------
__device__ __forceinline__ float tf32_rna(float x) {
    uint32_t r;
    asm("cvt.rna.tf32.f32 %0, %1;" : "=r"(r) : "f"(x));
    return __uint_as_float(r);
}

__device__ __forceinline__ void mma8(float c[4], const uint32_t a[4],
                                     const uint32_t b[2]) {
    asm volatile(
        "mma.sync.aligned.m16n8k8.row.col.f32.tf32.tf32.f32 "
        "{%0,%1,%2,%3}, {%4,%5,%6,%7}, {%8,%9}, {%0,%1,%2,%3};\n"
        : "+f"(c[0]), "+f"(c[1]), "+f"(c[2]), "+f"(c[3])
        : "r"(a[0]), "r"(a[1]), "r"(a[2]), "r"(a[3]),
          "r"(b[0]), "r"(b[1]));
}

__device__ __forceinline__ void cp_async16(uint32_t smem_addr, const void* gptr) {
    asm volatile("cp.async.cg.shared.global [%0], [%1], 16;\n"
                 :: "r"(smem_addr), "l"(gptr));
}
__device__ __forceinline__ void cp_commit() {
    asm volatile("cp.async.commit_group;\n");
}
__device__ __forceinline__ void cp_wait1() {
    asm volatile("cp.async.wait_group 1;\n");
}
__device__ __forceinline__ uint32_t smem_u32(const void* p) {
    return (uint32_t)__cvta_generic_to_shared(p);
}

// split raw fp32 -> (tf32 hi, residual lo) as uint bit patterns
__device__ __forceinline__ void split2(float x, uint32_t& hi, uint32_t& lo) {
    float h = tf32_rna(x);
    hi = __float_as_uint(h);
    lo = __float_as_uint(x - h);
}

// ---------------------------------------------------------------------------
// Projection GEMM v2: Y[m,n] = sum_k X[m,k]*W[n,k] + bias[n]
// 128x128 tile, BK=32, 256 thr (8 warps, 64x32 each), cp.async double buffer,
// raw fp32 smem, 3xTF32 split in registers.
// ---------------------------------------------------------------------------
#define GPAD 36
#define G_TILE_FLOATS (128 * GPAD)          // 4608
#define G_SMEM_FLOATS (4 * G_TILE_FLOATS)   // A0 A1 B0 B1 = 18432
#define G_SMEM_BYTES  (G_SMEM_FLOATS * 4)   // 73728

__global__ void __launch_bounds__(256)
gemm_tc_kernel(const float* __restrict__ X, const float* __restrict__ W,
               const float* __restrict__ bias, float* __restrict__ Y,
               int M, int N, int K)
{
    extern __shared__ float sm[];
    // layout: As[2] then Bs[2]
    float* As = sm;                       // [2][4608]
    float* Bs = sm + 2 * G_TILE_FLOATS;   // [2][4608]

    const int tid  = threadIdx.x;
    const int lane = tid & 31;
    const int w    = tid >> 5;
    const int wm   = w >> 2;
    const int wn   = w & 3;
    const int m0   = blockIdx.y * 128;
    const int n0   = blockIdx.x * 128;
    const int g    = lane >> 2;
    const int tg   = lane & 3;

    float c[4][4][4] = {};

    const uint32_t sbase = smem_u32(sm);

    // issue one 32-wide k-tile of A and B into buffer `buf`
    auto issue_tile = [&](int k0, int buf) {
        #pragma unroll
        for (int i = 0; i < 4; i++) {
            const int ch  = i * 256 + tid;     // 0..1023
            const int row = ch >> 3;
            const int seg = ch & 7;
            const uint32_t soff = (uint32_t)(row * GPAD + seg * 4) * 4u;
            cp_async16(sbase + (uint32_t)(buf * G_TILE_FLOATS * 4) + soff,
                       X + (size_t)(m0 + row) * K + k0 + seg * 4);
            cp_async16(sbase + (uint32_t)((2 + buf) * G_TILE_FLOATS * 4) + soff,
                       W + (size_t)(n0 + row) * K + k0 + seg * 4);
        }
    };

    issue_tile(0, 0);
    cp_commit();

    const int NT = K / 32;
    for (int kt = 0; kt < NT; kt++) {
        if (kt + 1 < NT) issue_tile((kt + 1) * 32, (kt + 1) & 1);
        cp_commit();
        cp_wait1();
        __syncthreads();

        const float* At = As + (kt & 1) * G_TILE_FLOATS;
        const float* Bt = Bs + (kt & 1) * G_TILE_FLOATS;

        #pragma unroll
        for (int ks = 0; ks < 4; ks++) {
            const int kk = ks * 8;
            uint32_t ahi[4][4], alo[4][4];
            #pragma unroll
            for (int mt = 0; mt < 4; mt++) {
                const int r = (wm * 64 + mt * 16 + g) * GPAD + kk;
                split2(At[r + tg],                ahi[mt][0], alo[mt][0]);
                split2(At[r + 8 * GPAD + tg],     ahi[mt][1], alo[mt][1]);
                split2(At[r + tg + 4],            ahi[mt][2], alo[mt][2]);
                split2(At[r + 8 * GPAD + tg + 4], ahi[mt][3], alo[mt][3]);
            }
            uint32_t bhi[4][2], blo[4][2];
            #pragma unroll
            for (int nt = 0; nt < 4; nt++) {
                const int r = (wn * 32 + nt * 8 + g) * GPAD + kk;
                split2(Bt[r + tg],     bhi[nt][0], blo[nt][0]);
                split2(Bt[r + tg + 4], bhi[nt][1], blo[nt][1]);
            }
            #pragma unroll
            for (int mt = 0; mt < 4; mt++)
                #pragma unroll
                for (int nt = 0; nt < 4; nt++) {
                    mma8(c[mt][nt], ahi[mt], bhi[nt]);
                    mma8(c[mt][nt], ahi[mt], blo[nt]);
                    mma8(c[mt][nt], alo[mt], bhi[nt]);
                }
        }
        __syncthreads();
    }

    #pragma unroll
    for (int mt = 0; mt < 4; mt++) {
        const int r0 = m0 + wm * 64 + mt * 16 + g;
        #pragma unroll
        for (int nt = 0; nt < 4; nt++) {
            const int cb = n0 + wn * 32 + nt * 8 + tg * 2;
            float2 bv = *(const float2*)(bias + cb);
            float2 v0, v1;
            v0.x = c[mt][nt][0] + bv.x; v0.y = c[mt][nt][1] + bv.y;
            v1.x = c[mt][nt][2] + bv.x; v1.y = c[mt][nt][3] + bv.y;
            *(float2*)(Y + (size_t)r0 * N + cb)       = v0;
            *(float2*)(Y + (size_t)(r0 + 8) * N + cb) = v1;
        }
    }
}

// ---------------------------------------------------------------------------
// Tensor-core flash attention.
// CTA: one (h,b), 128 query rows. 8 warps x 16 q-rows. 64-key tiles.
// QK: 3xTF32 (Q split persistent in regs, K split at frag load).
// PV: 3xTF32 (P split at frag load, V split at frag load).
// K/V tiles cp.async double-buffered. P round-trips via smem (per-warp rows).
// ---------------------------------------------------------------------------
#define AT_PAD 68
#define KV_TILE_FLOATS (64 * AT_PAD)          // 4352
// smem floats: K[2] V[2] P(128 rows)
#define AT_KS(buf) ((buf) * KV_TILE_FLOATS)
#define AT_VS(buf) ((2 + (buf)) * KV_TILE_FLOATS)
#define AT_PS      (4 * KV_TILE_FLOATS)
#define AT_SMEM_FLOATS (4 * KV_TILE_FLOATS + 128 * AT_PAD)   // 26112
#define AT_SMEM_BYTES  (AT_SMEM_FLOATS * 4)                  // 104448

__global__ void __launch_bounds__(256)
attn_tc_kernel(const float* __restrict__ Q, const float* __restrict__ Kp,
               const float* __restrict__ Vp, float* __restrict__ O)
{
    extern __shared__ float sm[];
    const int tid  = threadIdx.x;
    const int lane = tid & 31;
    const int w    = tid >> 5;
    const int g    = lane >> 2;
    const int tg   = lane & 3;

    const int qblk = blockIdx.x;        // 0..15
    const int hb   = blockIdx.y;        // 0..31
    const int h    = hb >> 1;
    const int b    = hb & 1;
    const int hoff = h * DHEAD;

    const uint32_t sbase = smem_u32(sm);

    // gmem row offset helper: tensor [S,B,D]
    auto gidx = [&](int row) -> size_t {
        return ((size_t)row * BATCH + b) * DMODEL + hoff;
    };

    // ---- stage Q tile (128 x 64) into P buffer, then load frags ----
    {
        #pragma unroll
        for (int i = 0; i < 8; i++) {
            const int ch  = i * 256 + tid;   // 0..2047
            const int row = ch >> 4;
            const int seg = ch & 15;
            float4 v = *(const float4*)(Q + gidx(qblk * 128 + row) + seg * 4);
            *(float4*)&sm[AT_PS + row * AT_PAD + seg * 4] = v;
        }
    }
    __syncthreads();

    uint32_t qhi[8][4], qlo[8][4];
    {
        const float* Qs = sm + AT_PS + (w * 16) * AT_PAD;
        #pragma unroll
        for (int ks = 0; ks < 8; ks++) {
            const int kk = ks * 8;
            split2(Qs[g * AT_PAD + kk + tg],           qhi[ks][0], qlo[ks][0]);
            split2(Qs[(g + 8) * AT_PAD + kk + tg],     qhi[ks][1], qlo[ks][1]);
            split2(Qs[g * AT_PAD + kk + tg + 4],       qhi[ks][2], qlo[ks][2]);
            split2(Qs[(g + 8) * AT_PAD + kk + tg + 4], qhi[ks][3], qlo[ks][3]);
        }
    }
    __syncthreads();

    // ---- K/V tile prefetch ----
    auto issue_kv = [&](int kb, int buf) {
        #pragma unroll
        for (int i = 0; i < 4; i++) {
            const int ch  = i * 256 + tid;   // 0..1023
            const int row = ch >> 4;
            const int seg = ch & 15;
            const uint32_t soff = (uint32_t)(row * AT_PAD + seg * 4) * 4u;
            const size_t go = gidx(kb + row) + seg * 4;
            cp_async16(sbase + (uint32_t)(AT_KS(buf) * 4) + soff, Kp + go);
            cp_async16(sbase + (uint32_t)(AT_VS(buf) * 4) + soff, Vp + go);
        }
    };

    issue_kv(0, 0);
    cp_commit();

    float o[8][4] = {};
    float mrow0 = -1e30f, mrow1 = -1e30f;
    float lrow0 = 0.0f,   lrow1 = 0.0f;
    const float scale = 0.125f;

    float* Pw = sm + AT_PS + (w * 16) * AT_PAD;   // this warp's P rows

    const int NKT = S_LEN / 64;   // 32
    for (int kt = 0; kt < NKT; kt++) {
        if (kt + 1 < NKT) issue_kv((kt + 1) * 64, (kt + 1) & 1);
        cp_commit();
        cp_wait1();
        __syncthreads();

        const float* Kt = sm + AT_KS(kt & 1);
        const float* Vt = sm + AT_VS(kt & 1);

        // ---- QK^T: scores s[nt][4] over 64 keys ----
        float s[8][4] = {};
        #pragma unroll
        for (int ks = 0; ks < 8; ks++) {
            const int kk = ks * 8;
            #pragma unroll
            for (int nt = 0; nt < 8; nt++) {
                const int r = (nt * 8 + g) * AT_PAD + kk;
                uint32_t bh[2], bl[2];
                split2(Kt[r + tg],     bh[0], bl[0]);
                split2(Kt[r + tg + 4], bh[1], bl[1]);
                mma8(s[nt], qhi[ks], bh);
                mma8(s[nt], qhi[ks], bl);
                mma8(s[nt], qlo[ks], bh);
            }
        }

        // ---- online softmax ----
        float mx0 = -1e30f, mx1 = -1e30f;
        #pragma unroll
        for (int nt = 0; nt < 8; nt++) {
            s[nt][0] *= scale; s[nt][1] *= scale;
            s[nt][2] *= scale; s[nt][3] *= scale;
            mx0 = fmaxf(mx0, fmaxf(s[nt][0], s[nt][1]));
            mx1 = fmaxf(mx1, fmaxf(s[nt][2], s[nt][3]));
        }
        mx0 = fmaxf(mx0, __shfl_xor_sync(0xffffffffu, mx0, 1));
        mx0 = fmaxf(mx0, __shfl_xor_sync(0xffffffffu, mx0, 2));
        mx1 = fmaxf(mx1, __shfl_xor_sync(0xffffffffu, mx1, 1));
        mx1 = fmaxf(mx1, __shfl_xor_sync(0xffffffffu, mx1, 2));

        const float mn0 = fmaxf(mrow0, mx0);
        const float mn1 = fmaxf(mrow1, mx1);
        const float corr0 = __expf(mrow0 - mn0);
        const float corr1 = __expf(mrow1 - mn1);
        mrow0 = mn0; mrow1 = mn1;

        float sum0 = 0.0f, sum1 = 0.0f;
        #pragma unroll
        for (int nt = 0; nt < 8; nt++) {
            s[nt][0] = __expf(s[nt][0] - mn0);
            s[nt][1] = __expf(s[nt][1] - mn0);
            s[nt][2] = __expf(s[nt][2] - mn1);
            s[nt][3] = __expf(s[nt][3] - mn1);
            sum0 += s[nt][0] + s[nt][1];
            sum1 += s[nt][2] + s[nt][3];
        }
        sum0 += __shfl_xor_sync(0xffffffffu, sum0, 1);
        sum0 += __shfl_xor_sync(0xffffffffu, sum0, 2);
        sum1 += __shfl_xor_sync(0xffffffffu, sum1, 1);
        sum1 += __shfl_xor_sync(0xffffffffu, sum1, 2);
        lrow0 = lrow0 * corr0 + sum0;
        lrow1 = lrow1 * corr1 + sum1;

        #pragma unroll
        for (int nt = 0; nt < 8; nt++) {
            o[nt][0] *= corr0; o[nt][1] *= corr0;
            o[nt][2] *= corr1; o[nt][3] *= corr1;
        }

        // ---- P -> smem (own warp rows only) ----
        #pragma unroll
        for (int nt = 0; nt < 8; nt++) {
            float2 p01; p01.x = s[nt][0]; p01.y = s[nt][1];
            float2 p23; p23.x = s[nt][2]; p23.y = s[nt][3];
            *(float2*)&Pw[g * AT_PAD + nt * 8 + 2 * tg]       = p01;
            *(float2*)&Pw[(g + 8) * AT_PAD + nt * 8 + 2 * tg] = p23;
        }
        __syncwarp();

        // ---- P @ V ----
        #pragma unroll
        for (int ks2 = 0; ks2 < 8; ks2++) {
            const int kk = ks2 * 8;
            uint32_t phi[4], plo[4];
            split2(Pw[g * AT_PAD + kk + tg],           phi[0], plo[0]);
            split2(Pw[(g + 8) * AT_PAD + kk + tg],     phi[1], plo[1]);
            split2(Pw[g * AT_PAD + kk + tg + 4],       phi[2], plo[2]);
            split2(Pw[(g + 8) * AT_PAD + kk + tg + 4], phi[3], plo[3]);
            #pragma unroll
            for (int nt = 0; nt < 8; nt++) {
                uint32_t vh[2], vl[2];
                split2(Vt[(kk + tg) * AT_PAD + nt * 8 + g],     vh[0], vl[0]);
                split2(Vt[(kk + tg + 4) * AT_PAD + nt * 8 + g], vh[1], vl[1]);
                mma8(o[nt], phi, vh);
                mma8(o[nt], phi, vl);
                mma8(o[nt], plo, vh);
            }
        }
        __syncwarp();
    }

    // ---- epilogue ----
    const float inv0 = 1.0f / lrow0;
    const float inv1 = 1.0f / lrow1;
    const int q0 = qblk * 128 + w * 16 + g;
    #pragma unroll
    for (int nt = 0; nt < 8; nt++) {
        float2 v0, v1;
        v0.x = o[nt][0] * inv0; v0.y = o[nt][1] * inv0;
        v1.x = o[nt][2] * inv1; v1.y = o[nt][3] * inv1;
        *(float2*)(O + gidx(q0) + nt * 8 + 2 * tg)     = v0;
        *(float2*)(O + gidx(q0 + 8) + nt * 8 + 2 * tg) = v1;
    }
}

// ---------------------------------------------------------------------------
extern "C" void kernel_launch(void* const* d_in, const int* in_sizes, int n_in,
                              void* d_out, int out_size)
{
    (void)in_sizes; (void)n_in; (void)out_size;
    const float* query = (const float*)d_in[0];
    const float* key   = (const float*)d_in[1];
    const float* value = (const float*)d_in[2];
    const float* Wq    = (const float*)d_in[3];
    const float* bq    = (const float*)d_in[4];
    const float* Wk    = (const float*)d_in[5];
    const float* bk    = (const float*)d_in[6];
    const float* Wv    = (const float*)d_in[7];
    const float* bv    = (const float*)d_in[8];
    const float* Wo    = (const float*)d_in[9];
    const float* bo    = (const float*)d_in[10];
    float* out = (float*)d_out;

    float *qp, *kp, *vp, *ap;
    cudaGetSymbolAddress((void**)&qp, g_q);
    cudaGetSymbolAddress((void**)&kp, g_k);
    cudaGetSymbolAddress((void**)&vp, g_v);
    cudaGetSymbolAddress((void**)&ap, g_attn);

    cudaFuncSetAttribute(gemm_tc_kernel,
                         cudaFuncAttributeMaxDynamicSharedMemorySize, G_SMEM_BYTES);
    cudaFuncSetAttribute(attn_tc_kernel,
                         cudaFuncAttributeMaxDynamicSharedMemorySize, AT_SMEM_BYTES);

    dim3 ggrid(DMODEL / 128, MROWS / 128);   // (8, 32)
    gemm_tc_kernel<<<ggrid, 256, G_SMEM_BYTES>>>(query, Wq, bq, qp, MROWS, DMODEL, DMODEL);
    gemm_tc_kernel<<<ggrid, 256, G_SMEM_BYTES>>>(key,   Wk, bk, kp, MROWS, DMODEL, DMODEL);
    gemm_tc_kernel<<<ggrid, 256, G_SMEM_BYTES>>>(value, Wv, bv, vp, MROWS, DMODEL, DMODEL);

    dim3 agrid(S_LEN / 128, NHEAD * BATCH);  // (16, 32)
    attn_tc_kernel<<<agrid, 256, AT_SMEM_BYTES>>>(qp, kp, vp, ap);

    gemm_tc_kernel<<<ggrid, 256, G_SMEM_BYTES>>>(ap, Wo, bo, out, MROWS, DMODEL, DMODEL);
}

// round 5
// speedup vs baseline: 2.6889x; 1.5202x over previous
#include <cuda_runtime.h>
#include <math.h>
#include <stdint.h>

// Problem constants (fixed by the reference)
#define S_LEN   2048
#define BATCH   2
#define DMODEL  1024
#define NHEAD   16
#define DHEAD   64
#define MROWS   (S_LEN * BATCH)

// Scratch (no allocation allowed)
__device__ float g_q[S_LEN * BATCH * DMODEL];
__device__ float g_k[S_LEN * BATCH * DMODEL];
__device__ float g_v[S_LEN * BATCH * DMODEL];
__device__ float g_attn[S_LEN * BATCH * DMODEL];
// tf32-rounded weights
__device__ float g_wq[DMODEL * DMODEL];
__device__ float g_wk[DMODEL * DMODEL];
__device__ float g_wv[DMODEL * DMODEL];
__device__ float g_wo[DMODEL * DMODEL];

// ---------------------------------------------------------------------------
// Helpers
// ---------------------------------------------------------------------------
__device__ __forceinline__ float tf32_rna(float x) {
    uint32_t r;
    asm("cvt.rna.tf32.f32 %0, %1;" : "=r"(r) : "f"(x));
    return __uint_as_float(r);
}

__device__ __forceinline__ void mma8(float c[4], const uint32_t a[4],
                                     const uint32_t b[2]) {
    asm volatile(
        "mma.sync.aligned.m16n8k8.row.col.f32.tf32.tf32.f32 "
        "{%0,%1,%2,%3}, {%4,%5,%6,%7}, {%8,%9}, {%0,%1,%2,%3};\n"
        : "+f"(c[0]), "+f"(c[1]), "+f"(c[2]), "+f"(c[3])
        : "r"(a[0]), "r"(a[1]), "r"(a[2]), "r"(a[3]),
          "r"(b[0]), "r"(b[1]));
}

__device__ __forceinline__ void cp_async16(uint32_t smem_addr, const void* gptr) {
    asm volatile("cp.async.cg.shared.global [%0], [%1], 16;\n"
                 :: "r"(smem_addr), "l"(gptr));
}
__device__ __forceinline__ void cp_commit() {
    asm volatile("cp.async.commit_group;\n");
}
__device__ __forceinline__ void cp_wait1() {
    asm volatile("cp.async.wait_group 1;\n");
}
__device__ __forceinline__ uint32_t smem_u32(const void* p) {
    return (uint32_t)__cvta_generic_to_shared(p);
}

__device__ __forceinline__ void split2(float x, uint32_t& hi, uint32_t& lo) {
    float h = tf32_rna(x);
    hi = __float_as_uint(h);
    lo = __float_as_uint(x - h);
}

// ---------------------------------------------------------------------------
// Weight pre-rounding: Whi = rna(W). ~1M floats each, trivially HBM-bound.
// ---------------------------------------------------------------------------
__global__ void __launch_bounds__(256)
round_w_kernel(const float* __restrict__ w, float* __restrict__ o)
{
    const int i = (blockIdx.x * 256 + threadIdx.x) * 4;
    float4 v = *(const float4*)(w + i);
    v.x = tf32_rna(v.x); v.y = tf32_rna(v.y);
    v.z = tf32_rna(v.z); v.w = tf32_rna(v.w);
    *(float4*)(o + i) = v;
}

// ---------------------------------------------------------------------------
// Projection GEMM v3: Y[m,n] = sum_k X[m,k]*Whi[n,k] + bias[n]
// Whi pre-rounded to tf32 -> raw B fragments, 2-pass (xhi*B + xlo*B).
// 128x128 tile, BK=32, 256 thr, cp.async double buffer.
// ROUND_OUT: epilogue rounds output to tf32 (for K/V feeding attention).
// ---------------------------------------------------------------------------
#define GPAD 36
#define G_TILE_FLOATS (128 * GPAD)
#define G_SMEM_FLOATS (4 * G_TILE_FLOATS)
#define G_SMEM_BYTES  (G_SMEM_FLOATS * 4)   // 73728

template<bool ROUND_OUT>
__global__ void __launch_bounds__(256)
gemm_tc_kernel(const float* __restrict__ X, const float* __restrict__ W,
               const float* __restrict__ bias, float* __restrict__ Y,
               int M, int N, int K)
{
    extern __shared__ float sm[];
    float* As = sm;
    float* Bs = sm + 2 * G_TILE_FLOATS;

    const int tid  = threadIdx.x;
    const int lane = tid & 31;
    const int w    = tid >> 5;
    const int wm   = w >> 2;
    const int wn   = w & 3;
    const int m0   = blockIdx.y * 128;
    const int n0   = blockIdx.x * 128;
    const int g    = lane >> 2;
    const int tg   = lane & 3;

    float c[4][4][4] = {};
    const uint32_t sbase = smem_u32(sm);

    auto issue_tile = [&](int k0, int buf) {
        #pragma unroll
        for (int i = 0; i < 4; i++) {
            const int ch  = i * 256 + tid;
            const int row = ch >> 3;
            const int seg = ch & 7;
            const uint32_t soff = (uint32_t)(row * GPAD + seg * 4) * 4u;
            cp_async16(sbase + (uint32_t)(buf * G_TILE_FLOATS * 4) + soff,
                       X + (size_t)(m0 + row) * K + k0 + seg * 4);
            cp_async16(sbase + (uint32_t)((2 + buf) * G_TILE_FLOATS * 4) + soff,
                       W + (size_t)(n0 + row) * K + k0 + seg * 4);
        }
    };

    issue_tile(0, 0);
    cp_commit();

    const int NT = K / 32;
    for (int kt = 0; kt < NT; kt++) {
        if (kt + 1 < NT) issue_tile((kt + 1) * 32, (kt + 1) & 1);
        cp_commit();
        cp_wait1();
        __syncthreads();

        const float* At = As + (kt & 1) * G_TILE_FLOATS;
        const float* Bt = Bs + (kt & 1) * G_TILE_FLOATS;

        #pragma unroll
        for (int ks = 0; ks < 4; ks++) {
            const int kk = ks * 8;
            uint32_t ahi[4][4], alo[4][4];
            #pragma unroll
            for (int mt = 0; mt < 4; mt++) {
                const int r = (wm * 64 + mt * 16 + g) * GPAD + kk;
                split2(At[r + tg],                ahi[mt][0], alo[mt][0]);
                split2(At[r + 8 * GPAD + tg],     ahi[mt][1], alo[mt][1]);
                split2(At[r + tg + 4],            ahi[mt][2], alo[mt][2]);
                split2(At[r + 8 * GPAD + tg + 4], ahi[mt][3], alo[mt][3]);
            }
            uint32_t bh[4][2];
            #pragma unroll
            for (int nt = 0; nt < 4; nt++) {
                const int r = (wn * 32 + nt * 8 + g) * GPAD + kk;
                bh[nt][0] = __float_as_uint(Bt[r + tg]);
                bh[nt][1] = __float_as_uint(Bt[r + tg + 4]);
            }
            #pragma unroll
            for (int mt = 0; mt < 4; mt++)
                #pragma unroll
                for (int nt = 0; nt < 4; nt++) {
                    mma8(c[mt][nt], ahi[mt], bh[nt]);
                    mma8(c[mt][nt], alo[mt], bh[nt]);
                }
        }
        __syncthreads();
    }

    #pragma unroll
    for (int mt = 0; mt < 4; mt++) {
        const int r0 = m0 + wm * 64 + mt * 16 + g;
        #pragma unroll
        for (int nt = 0; nt < 4; nt++) {
            const int cb = n0 + wn * 32 + nt * 8 + tg * 2;
            float2 bv = *(const float2*)(bias + cb);
            float2 v0, v1;
            v0.x = c[mt][nt][0] + bv.x; v0.y = c[mt][nt][1] + bv.y;
            v1.x = c[mt][nt][2] + bv.x; v1.y = c[mt][nt][3] + bv.y;
            if (ROUND_OUT) {
                v0.x = tf32_rna(v0.x); v0.y = tf32_rna(v0.y);
                v1.x = tf32_rna(v1.x); v1.y = tf32_rna(v1.y);
            }
            *(float2*)(Y + (size_t)r0 * N + cb)       = v0;
            *(float2*)(Y + (size_t)(r0 + 8) * N + cb) = v1;
        }
    }
}

// ---------------------------------------------------------------------------
// Tensor-core flash attention v2.
// K/V in gmem are ALREADY tf32-rounded -> raw fragments, no split.
// QK: qhi*k + qlo*k (2-pass).  PV: phi*v + plo*v (2-pass).
// ---------------------------------------------------------------------------
#define AT_PAD 68
#define KV_TILE_FLOATS (64 * AT_PAD)
#define AT_KS(buf) ((buf) * KV_TILE_FLOATS)
#define AT_VS(buf) ((2 + (buf)) * KV_TILE_FLOATS)
#define AT_PS      (4 * KV_TILE_FLOATS)
#define AT_SMEM_FLOATS (4 * KV_TILE_FLOATS + 128 * AT_PAD)
#define AT_SMEM_BYTES  (AT_SMEM_FLOATS * 4)

__global__ void __launch_bounds__(256)
attn_tc_kernel(const float* __restrict__ Q, const float* __restrict__ Kp,
               const float* __restrict__ Vp, float* __restrict__ O)
{
    extern __shared__ float sm[];
    const int tid  = threadIdx.x;
    const int lane = tid & 31;
    const int w    = tid >> 5;
    const int g    = lane >> 2;
    const int tg   = lane & 3;

    const int qblk = blockIdx.x;
    const int hb   = blockIdx.y;
    const int h    = hb >> 1;
    const int b    = hb & 1;
    const int hoff = h * DHEAD;

    const uint32_t sbase = smem_u32(sm);

    auto gidx = [&](int row) -> size_t {
        return ((size_t)row * BATCH + b) * DMODEL + hoff;
    };

    // stage Q tile into P buffer, load persistent split fragments
    {
        #pragma unroll
        for (int i = 0; i < 8; i++) {
            const int ch  = i * 256 + tid;
            const int row = ch >> 4;
            const int seg = ch & 15;
            float4 v = *(const float4*)(Q + gidx(qblk * 128 + row) + seg * 4);
            *(float4*)&sm[AT_PS + row * AT_PAD + seg * 4] = v;
        }
    }
    __syncthreads();

    uint32_t qhi[8][4], qlo[8][4];
    {
        const float* Qs = sm + AT_PS + (w * 16) * AT_PAD;
        #pragma unroll
        for (int ks = 0; ks < 8; ks++) {
            const int kk = ks * 8;
            split2(Qs[g * AT_PAD + kk + tg],           qhi[ks][0], qlo[ks][0]);
            split2(Qs[(g + 8) * AT_PAD + kk + tg],     qhi[ks][1], qlo[ks][1]);
            split2(Qs[g * AT_PAD + kk + tg + 4],       qhi[ks][2], qlo[ks][2]);
            split2(Qs[(g + 8) * AT_PAD + kk + tg + 4], qhi[ks][3], qlo[ks][3]);
        }
    }
    __syncthreads();

    auto issue_kv = [&](int kb, int buf) {
        #pragma unroll
        for (int i = 0; i < 4; i++) {
            const int ch  = i * 256 + tid;
            const int row = ch >> 4;
            const int seg = ch & 15;
            const uint32_t soff = (uint32_t)(row * AT_PAD + seg * 4) * 4u;
            const size_t go = gidx(kb + row) + seg * 4;
            cp_async16(sbase + (uint32_t)(AT_KS(buf) * 4) + soff, Kp + go);
            cp_async16(sbase + (uint32_t)(AT_VS(buf) * 4) + soff, Vp + go);
        }
    };

    issue_kv(0, 0);
    cp_commit();

    float o[8][4] = {};
    float mrow0 = -1e30f, mrow1 = -1e30f;
    float lrow0 = 0.0f,   lrow1 = 0.0f;
    const float scale = 0.125f;

    float* Pw = sm + AT_PS + (w * 16) * AT_PAD;

    const int NKT = S_LEN / 64;
    for (int kt = 0; kt < NKT; kt++) {
        if (kt + 1 < NKT) issue_kv((kt + 1) * 64, (kt + 1) & 1);
        cp_commit();
        cp_wait1();
        __syncthreads();

        const float* Kt = sm + AT_KS(kt & 1);
        const float* Vt = sm + AT_VS(kt & 1);

        // ---- QK^T (K already tf32-rounded: raw fragments) ----
        float s[8][4] = {};
        #pragma unroll
        for (int ks = 0; ks < 8; ks++) {
            const int kk = ks * 8;
            #pragma unroll
            for (int nt = 0; nt < 8; nt++) {
                const int r = (nt * 8 + g) * AT_PAD + kk;
                uint32_t bh[2];
                bh[0] = __float_as_uint(Kt[r + tg]);
                bh[1] = __float_as_uint(Kt[r + tg + 4]);
                mma8(s[nt], qhi[ks], bh);
                mma8(s[nt], qlo[ks], bh);
            }
        }

        // ---- online softmax ----
        float mx0 = -1e30f, mx1 = -1e30f;
        #pragma unroll
        for (int nt = 0; nt < 8; nt++) {
            s[nt][0] *= scale; s[nt][1] *= scale;
            s[nt][2] *= scale; s[nt][3] *= scale;
            mx0 = fmaxf(mx0, fmaxf(s[nt][0], s[nt][1]));
            mx1 = fmaxf(mx1, fmaxf(s[nt][2], s[nt][3]));
        }
        mx0 = fmaxf(mx0, __shfl_xor_sync(0xffffffffu, mx0, 1));
        mx0 = fmaxf(mx0, __shfl_xor_sync(0xffffffffu, mx0, 2));
        mx1 = fmaxf(mx1, __shfl_xor_sync(0xffffffffu, mx1, 1));
        mx1 = fmaxf(mx1, __shfl_xor_sync(0xffffffffu, mx1, 2));

        const float mn0 = fmaxf(mrow0, mx0);
        const float mn1 = fmaxf(mrow1, mx1);
        const float corr0 = __expf(mrow0 - mn0);
        const float corr1 = __expf(mrow1 - mn1);
        mrow0 = mn0; mrow1 = mn1;

        float sum0 = 0.0f, sum1 = 0.0f;
        #pragma unroll
        for (int nt = 0; nt < 8; nt++) {
            s[nt][0] = __expf(s[nt][0] - mn0);
            s[nt][1] = __expf(s[nt][1] - mn0);
            s[nt][2] = __expf(s[nt][2] - mn1);
            s[nt][3] = __expf(s[nt][3] - mn1);
            sum0 += s[nt][0] + s[nt][1];
            sum1 += s[nt][2] + s[nt][3];
        }
        sum0 += __shfl_xor_sync(0xffffffffu, sum0, 1);
        sum0 += __shfl_xor_sync(0xffffffffu, sum0, 2);
        sum1 += __shfl_xor_sync(0xffffffffu, sum1, 1);
        sum1 += __shfl_xor_sync(0xffffffffu, sum1, 2);
        lrow0 = lrow0 * corr0 + sum0;
        lrow1 = lrow1 * corr1 + sum1;

        #pragma unroll
        for (int nt = 0; nt < 8; nt++) {
            o[nt][0] *= corr0; o[nt][1] *= corr0;
            o[nt][2] *= corr1; o[nt][3] *= corr1;
        }

        // ---- P -> smem (own warp rows) ----
        #pragma unroll
        for (int nt = 0; nt < 8; nt++) {
            float2 p01; p01.x = s[nt][0]; p01.y = s[nt][1];
            float2 p23; p23.x = s[nt][2]; p23.y = s[nt][3];
            *(float2*)&Pw[g * AT_PAD + nt * 8 + 2 * tg]       = p01;
            *(float2*)&Pw[(g + 8) * AT_PAD + nt * 8 + 2 * tg] = p23;
        }
        __syncwarp();

        // ---- P @ V (V already tf32-rounded: raw fragments) ----
        #pragma unroll
        for (int ks2 = 0; ks2 < 8; ks2++) {
            const int kk = ks2 * 8;
            uint32_t phi[4], plo[4];
            split2(Pw[g * AT_PAD + kk + tg],           phi[0], plo[0]);
            split2(Pw[(g + 8) * AT_PAD + kk + tg],     phi[1], plo[1]);
            split2(Pw[g * AT_PAD + kk + tg + 4],       phi[2], plo[2]);
            split2(Pw[(g + 8) * AT_PAD + kk + tg + 4], phi[3], plo[3]);
            #pragma unroll
            for (int nt = 0; nt < 8; nt++) {
                uint32_t vh[2];
                vh[0] = __float_as_uint(Vt[(kk + tg) * AT_PAD + nt * 8 + g]);
                vh[1] = __float_as_uint(Vt[(kk + tg + 4) * AT_PAD + nt * 8 + g]);
                mma8(o[nt], phi, vh);
                mma8(o[nt], plo, vh);
            }
        }
        __syncwarp();
    }

    const float inv0 = 1.0f / lrow0;
    const float inv1 = 1.0f / lrow1;
    const int q0 = qblk * 128 + w * 16 + g;
    #pragma unroll
    for (int nt = 0; nt < 8; nt++) {
        float2 v0, v1;
        v0.x = o[nt][0] * inv0; v0.y = o[nt][1] * inv0;
        v1.x = o[nt][2] * inv1; v1.y = o[nt][3] * inv1;
        *(float2*)(O + gidx(q0) + nt * 8 + 2 * tg)     = v0;
        *(float2*)(O + gidx(q0 + 8) + nt * 8 + 2 * tg) = v1;
    }
}

// ---------------------------------------------------------------------------
extern "C" void kernel_launch(void* const* d_in, const int* in_sizes, int n_in,
                              void* d_out, int out_size)
{
    (void)in_sizes; (void)n_in; (void)out_size;
    const float* query = (const float*)d_in[0];
    const float* key   = (const float*)d_in[1];
    const float* value = (const float*)d_in[2];
    const float* Wq    = (const float*)d_in[3];
    const float* bq    = (const float*)d_in[4];
    const float* Wk    = (const float*)d_in[5];
    const float* bk    = (const float*)d_in[6];
    const float* Wv    = (const float*)d_in[7];
    const float* bv    = (const float*)d_in[8];
    const float* Wo    = (const float*)d_in[9];
    const float* bo    = (const float*)d_in[10];
    float* out = (float*)d_out;

    float *qp, *kp, *vp, *ap, *wq, *wk, *wv, *wo;
    cudaGetSymbolAddress((void**)&qp, g_q);
    cudaGetSymbolAddress((void**)&kp, g_k);
    cudaGetSymbolAddress((void**)&vp, g_v);
    cudaGetSymbolAddress((void**)&ap, g_attn);
    cudaGetSymbolAddress((void**)&wq, g_wq);
    cudaGetSymbolAddress((void**)&wk, g_wk);
    cudaGetSymbolAddress((void**)&wv, g_wv);
    cudaGetSymbolAddress((void**)&wo, g_wo);

    cudaFuncSetAttribute(gemm_tc_kernel<false>,
                         cudaFuncAttributeMaxDynamicSharedMemorySize, G_SMEM_BYTES);
    cudaFuncSetAttribute(gemm_tc_kernel<true>,
                         cudaFuncAttributeMaxDynamicSharedMemorySize, G_SMEM_BYTES);
    cudaFuncSetAttribute(attn_tc_kernel,
                         cudaFuncAttributeMaxDynamicSharedMemorySize, AT_SMEM_BYTES);

    // Pre-round weights to tf32 (enables raw B fragments, 2-pass GEMM)
    const int welems = DMODEL * DMODEL;
    round_w_kernel<<<welems / (256 * 4), 256>>>(Wq, wq);
    round_w_kernel<<<welems / (256 * 4), 256>>>(Wk, wk);
    round_w_kernel<<<welems / (256 * 4), 256>>>(Wv, wv);
    round_w_kernel<<<welems / (256 * 4), 256>>>(Wo, wo);

    dim3 ggrid(DMODEL / 128, MROWS / 128);
    gemm_tc_kernel<false><<<ggrid, 256, G_SMEM_BYTES>>>(query, wq, bq, qp, MROWS, DMODEL, DMODEL);
    gemm_tc_kernel<true><<<ggrid, 256, G_SMEM_BYTES>>>(key,   wk, bk, kp, MROWS, DMODEL, DMODEL);
    gemm_tc_kernel<true><<<ggrid, 256, G_SMEM_BYTES>>>(value, wv, bv, vp, MROWS, DMODEL, DMODEL);

    dim3 agrid(S_LEN / 128, NHEAD * BATCH);
    attn_tc_kernel<<<agrid, 256, AT_SMEM_BYTES>>>(qp, kp, vp, ap);

    gemm_tc_kernel<false><<<ggrid, 256, G_SMEM_BYTES>>>(ap, wo, bo, out, MROWS, DMODEL, DMODEL);
}